// round 12
// baseline (speedup 1.0000x reference)
#include <cuda_runtime.h>
#include <cuda_bf16.h>

// JointBilateral upsample, S=4, K=5. One thread = 8 output pixels: rows
// {4p+gsel, 4p+gsel+2}, cols 4q..4q+3. Both rows share tap values, x values
// and index math. No smem, no barrier; taps are warm-L2/L1 hit loads.
// gsel=1 threads get the first tap free (rowA IS guidance row 4p+1).
//
// e(tap) = exp(-0.125*||g_tap - g_ctr||^2) * exp(-0.005*((i-2)^2+(j-2)^2))
// out = sum(e * wgt[4-i][4-j] * x_tap) / sum(e)
// exp via cubic poly (z in [0,0.094], err <= 3.3e-6); divide via MUFU.

#define CH  (512 * 512)
#define E1  0.9950124791926823f   /* exp(-0.005) */
#define E4  0.9801986733067553f   /* exp(-0.020) */

__device__ __forceinline__ float exp_neg_small(float z)
{
    float p = fmaf(-0.16666667f, z, 0.5f);
    p = fmaf(p, z, -1.0f);
    return fmaf(p, z, 1.0f);
}

__global__ void __launch_bounds__(128) jb_kernel(
    const float* __restrict__ x,
    const float* __restrict__ g,
    const float* __restrict__ wgt,
    float* __restrict__ out)
{
    int tid  = threadIdx.x;
    int ql   = tid & 63;
    int gsel = tid >> 6;              // 0: rows {0,2}; 1: rows {1,3}
    int blk  = blockIdx.x;            // 1024 = 2 qh * 128 p * 4 b
    int qh   = blk & 1;
    int p    = (blk >> 1) & 127;
    int b    = blk >> 8;
    int q    = qh * 64 + ql;

    const float* gb = g + (size_t)b * 3 * CH;
    const float* xb = x + b * (128 * 128);

    bool row2 = (p < 127);
    bool col2 = (q < 127);
    int dq = col2 ? 4 : 0;
    int cq = col2 ? 1 : 0;

    int rowA = (4 * p + gsel) * 512 + 4 * q;
    int rowB = rowA + 2 * 512;
    int o00  = (4 * p + 1) * 512 + 4 * q + 1;

    // ---- front-loaded loads ----
    float4 a0 = *(const float4*)(gb + rowA);
    float4 a1 = *(const float4*)(gb + CH + rowA);
    float4 a2 = *(const float4*)(gb + 2 * CH + rowA);
    float4 e0 = *(const float4*)(gb + rowB);
    float4 e1 = *(const float4*)(gb + CH + rowB);
    float4 e2 = *(const float4*)(gb + 2 * CH + rowB);

    // first tap: gsel==1 has it in registers (rowA == guidance row 4p+1)
    float t0, t1, t2;
    if (gsel == 1) {
        t0 = a0.y; t1 = a1.y; t2 = a2.y;
    } else {
        t0 = gb[o00];
        t1 = gb[o00 + CH];
        t2 = gb[o00 + 2 * CH];
    }
    float u0 = gb[o00 + dq];
    float u1 = gb[o00 + dq + CH];
    float u2 = gb[o00 + dq + 2 * CH];

    int xo = p * 128 + q;
    float x00 = xb[xo];
    float x01 = xb[xo + cq];

    // second-row taps only needed by gsel==1 (row 4p+3); warp-uniform branch
    float v0 = 0.f, v1 = 0.f, v2 = 0.f, z0 = 0.f, z1 = 0.f, z2 = 0.f;
    float x10 = 0.f, x11 = 0.f;
    if (gsel == 1) {
        int dr = row2 ? 4 * 512 : 0;
        v0 = gb[o00 + dr];
        v1 = gb[o00 + dr + CH];
        v2 = gb[o00 + dr + 2 * CH];
        z0 = gb[o00 + dr + dq];
        z1 = gb[o00 + dr + dq + CH];
        z2 = gb[o00 + dr + dq + 2 * CH];
        int cp = row2 ? 1 : 0;
        x10 = xb[xo + cp * 128];
        x11 = xb[xo + cp * 128 + cq];
    }

    const float espC[4]    = {E1, 1.0f, E1, E4};
    const float espSTab[4] = {E1, 1.0f, E1, E4};
    size_t obase = (size_t)b * CH;

    // ================= row A (sp = gsel) =================
    {
        int sp = gsel;
        float espS = espSTab[sp];
        const float* wr = wgt + (sp + 1) * 5;
        float wAr[4] = {wr[1] * x00, wr[2] * x00, wr[3] * x00, wr[4] * x00};
        float wCol = wr[0] * x01;
        float ctr0[4] = {a0.x, a0.y, a0.z, a0.w};
        float ctr1[4] = {a1.x, a1.y, a1.z, a1.w};
        float ctr2[4] = {a2.x, a2.y, a2.z, a2.w};

        float num[4], den[4];
#pragma unroll
        for (int r = 0; r < 4; r++) {
            float d0 = t0 - ctr0[r];
            float d1 = t1 - ctr1[r];
            float d2 = t2 - ctr2[r];
            float zv = 0.125f * fmaf(d0, d0, fmaf(d1, d1, d2 * d2));
            float e = exp_neg_small(zv) * (espS * espC[r]);
            den[r] = e;
            num[r] = e * wAr[r];
        }
        {
            float h0 = u0 - ctr0[3];
            float h1 = u1 - ctr1[3];
            float h2 = u2 - ctr2[3];
            float zv = 0.125f * fmaf(h0, h0, fmaf(h1, h1, h2 * h2));
            float e3 = exp_neg_small(zv) * (espS * E4);
            if (col2) { den[3] += e3; num[3] += e3 * wCol; }
        }
        float4 o = make_float4(__fdividef(num[0], den[0]),
                               __fdividef(num[1], den[1]),
                               __fdividef(num[2], den[2]),
                               __fdividef(num[3], den[3]));
        *(float4*)(out + obase + rowA) = o;
    }

    // ================= row B (sp = gsel + 2) =================
    {
        int sp = gsel + 2;
        float espS = espSTab[sp];
        const float* wr = wgt + (sp + 1) * 5;
        float wAr[4] = {wr[1] * x00, wr[2] * x00, wr[3] * x00, wr[4] * x00};
        float wCol = wr[0] * x01;
        float ctr0[4] = {e0.x, e0.y, e0.z, e0.w};
        float ctr1[4] = {e1.x, e1.y, e1.z, e1.w};
        float ctr2[4] = {e2.x, e2.y, e2.z, e2.w};

        float num[4], den[4];
#pragma unroll
        for (int r = 0; r < 4; r++) {
            float d0 = t0 - ctr0[r];
            float d1 = t1 - ctr1[r];
            float d2 = t2 - ctr2[r];
            float zv = 0.125f * fmaf(d0, d0, fmaf(d1, d1, d2 * d2));
            float e = exp_neg_small(zv) * (espS * espC[r]);
            den[r] = e;
            num[r] = e * wAr[r];
        }
        {
            float h0 = u0 - ctr0[3];
            float h1 = u1 - ctr1[3];
            float h2 = u2 - ctr2[3];
            float zv = 0.125f * fmaf(h0, h0, fmaf(h1, h1, h2 * h2));
            float e3 = exp_neg_small(zv) * (espS * E4);
            if (col2) { den[3] += e3; num[3] += e3 * wCol; }
        }

        if (gsel == 1 && row2) {      // row 4p+3: second-row taps (warp-uniform)
#pragma unroll
            for (int r = 0; r < 4; r++) {
                float f0 = v0 - ctr0[r];
                float f1 = v1 - ctr1[r];
                float f2 = v2 - ctr2[r];
                float zv = 0.125f * fmaf(f0, f0, fmaf(f1, f1, f2 * f2));
                float e2x = exp_neg_small(zv) * (E4 * espC[r]);
                den[r] += e2x;
                num[r] += e2x * wgt[r + 1] * x10;
            }
            if (col2) {               // corner tap
                float k0 = z0 - ctr0[3];
                float k1 = z1 - ctr1[3];
                float k2 = z2 - ctr2[3];
                float zz = 0.125f * fmaf(k0, k0, fmaf(k1, k1, k2 * k2));
                float e4x = exp_neg_small(zz) * (E4 * E4);
                den[3] += e4x;
                num[3] += e4x * wgt[0] * x11;
            }
        }

        float4 o = make_float4(__fdividef(num[0], den[0]),
                               __fdividef(num[1], den[1]),
                               __fdividef(num[2], den[2]),
                               __fdividef(num[3], den[3]));
        *(float4*)(out + obase + rowB) = o;
    }
}

extern "C" void kernel_launch(void* const* d_in, const int* in_sizes, int n_in,
                              void* d_out, int out_size)
{
    const float* x   = (const float*)d_in[0];
    const float* g   = (const float*)d_in[1];
    const float* wgt = (const float*)d_in[2];
    float* out = (float*)d_out;

    // 1024 blocks: 2 qh * 128 p * 4 b ; 128 threads: 2 row-groups * 64 q
    jb_kernel<<<1024, 128>>>(x, g, wgt, out);
}